// round 17
// baseline (speedup 1.0000x reference)
#include <cuda_runtime.h>
#include <math.h>

#define N_K   256
#define N_T   128
#define N_C   32
#define N_D   10
#define N_SPK 1000000
#define LOG2PI 1.8378770664093453f

// NESTED coefficient row per component (68 floats = 34 pairs = 17 quads):
// pairs  0..24 : t-stage j-pairs, rows i=0..8 in order; even rows start j=i
//                (diag included), odd rows start j=i+1 (diag split out)
// pairs 25..27 : odd/last diagonals: (-P11/2,-P33/2),(-P55/2,-P77/2),(-P99/2,0)
//                (the -P99/2 lo half is consumed as a scalar vs s9^2)
// pairs 28..32 : linear coeffs (P @ mu) vs s-pairs
// pair  33     : (K_c - M, 0)
#define ROWF 68
#define ROWP 34
#define ROWQ 17
#define NCONSTQ 10         // quads 0..9 from constant bank, 10..16 from SMEM

#define MAIN_BLOCK 128
#define N_HALF (N_SPK / 2)                       // 500000 threads, 2 spikes each
#define NBLOCKS ((N_HALF + MAIN_BLOCK - 1) / MAIN_BLOCK)

typedef unsigned long long u64;

__device__ __align__(16) u64 g_W[N_C * ROWP];
__constant__ __align__(16) u64 c_W[N_C * ROWP];
__device__ float g_prior;
__device__ float g_M;
__device__ float g_logpi[N_K * N_T * N_C];       // (k,t,c)-major, 4 MB, L2-resident
__device__ float g_partial[NBLOCKS];
__device__ unsigned int g_count;

// ---- f32x2 packed-math helpers (Blackwell dual-fp32 pipe, PTX-only) ----
__device__ __forceinline__ u64 pk2(float lo, float hi) {
    u64 r; asm("mov.b64 %0,{%1,%2};" : "=l"(r) : "f"(lo), "f"(hi)); return r;
}
__device__ __forceinline__ void fma2(u64& d, u64 a, u64 b) {
    asm("fma.rn.f32x2 %0,%1,%2,%3;" : "=l"(d) : "l"(a), "l"(b), "l"(d));
}
__device__ __forceinline__ u64 mul2(u64 a, u64 b) {
    u64 r; asm("mul.rn.f32x2 %0,%1,%2;" : "=l"(r) : "l"(a), "l"(b)); return r;
}
__device__ __forceinline__ u64 add2(u64 a, u64 b) {
    u64 r; asm("add.rn.f32x2 %0,%1,%2;" : "=l"(r) : "l"(a), "l"(b)); return r;
}
__device__ __forceinline__ float2 upk(u64 a) {
    float2 v; asm("mov.b64 {%0,%1},%2;" : "=f"(v.x), "=f"(v.y) : "l"(a)); return v;
}

// ---------------------------------------------------------------------------
// Kernel 1: log_pi table (warp per (k,t), lane = component) + one setup block.
// ---------------------------------------------------------------------------
__global__ void logpi_setup_kernel(const float* __restrict__ y,
                                   const float* __restrict__ b_mu,
                                   const float* __restrict__ beta_mu,
                                   const float* __restrict__ means,
                                   const float* __restrict__ covs,
                                   const float* __restrict__ b_log_sig,
                                   const float* __restrict__ beta_log_sig) {
    if (blockIdx.x == gridDim.x - 1) {
        int tid = threadIdx.x;
        if (tid == 0) g_count = 0;

        if (tid < N_C) {
            const float* cov = covs + tid * N_D * N_D;
            const float* mu  = means + tid * N_D;

            float L[N_D][N_D];
            float logdet = 0.0f;
            for (int j = 0; j < N_D; j++) {
                float sdiag = cov[j * N_D + j];
                for (int k = 0; k < j; k++) sdiag -= L[j][k] * L[j][k];
                float d = sqrtf(sdiag);
                L[j][j] = d;
                logdet += 2.0f * logf(d);
                for (int i = j + 1; i < N_D; i++) {
                    float v = cov[i * N_D + j];
                    for (int k = 0; k < j; k++) v -= L[i][k] * L[j][k];
                    L[i][j] = v / d;
                }
            }
            float Li[N_D][N_D];
            for (int j = 0; j < N_D; j++)
                for (int i = 0; i < N_D; i++) {
                    if (i < j) { Li[i][j] = 0.0f; continue; }
                    float v = (i == j) ? 1.0f : 0.0f;
                    for (int k = j; k < i; k++) v -= L[i][k] * Li[k][j];
                    Li[i][j] = v / L[i][i];
                }
            float P[N_D][N_D];
            for (int i = 0; i < N_D; i++)
                for (int j = 0; j < N_D; j++) {
                    float v = 0.0f;
                    int k0 = (i > j) ? i : j;
                    for (int k = k0; k < N_D; k++) v += Li[k][i] * Li[k][j];
                    P[i][j] = v;
                }
            float w[N_D], quad = 0.0f;
            for (int i = 0; i < N_D; i++) {
                float v = 0.0f;
                for (int j = 0; j < N_D; j++) v += P[i][j] * mu[j];
                w[i] = v;
                quad += v * mu[i];
            }
            float kp = -0.5f * (logdet + (float)N_D * LOG2PI);
            float M = kp;
            #pragma unroll
            for (int o = 16; o > 0; o >>= 1)
                M = fmaxf(M, __shfl_xor_sync(0xffffffffu, M, o));
            if (tid == 0) g_M = M;

            float* Wc = (float*)g_W + tid * ROWF;
            // t-stage pairs, rows 0..8: even rows from j=i (incl diag),
            // odd rows from j=i+1 (diag split out). 25 pairs = 50 floats.
            int u = 0;
            for (int i = 0; i < 9; i++) {
                int jstart = (i % 2 == 0) ? i : i + 1;
                for (int j = jstart; j < N_D; j += 2) {
                    Wc[u++] = (i == j) ? (-0.5f * P[i][i]) : (-P[i][j]);
                    Wc[u++] = -P[i][j + 1];          // j+1 > i always here
                }
            }
            // u == 50: odd diagonals + row-9 diagonal
            Wc[50] = -0.5f * P[1][1];
            Wc[51] = -0.5f * P[3][3];
            Wc[52] = -0.5f * P[5][5];
            Wc[53] = -0.5f * P[7][7];
            Wc[54] = -0.5f * P[9][9];
            Wc[55] = 0.0f;
            for (int i = 0; i < N_D; i++) Wc[56 + i] = w[i];
            Wc[66] = (kp - 0.5f * quad) - M;         // K_c - M
            Wc[67] = 0.0f;
        }

        __shared__ float red[256];
        float acc = 0.0f;
        for (int i = tid; i < N_C; i += 256)
            acc += b_log_sig[i] - 0.5f * b_mu[i] * b_mu[i];
        for (int i = tid; i < N_C * N_T; i += 256)
            acc += beta_log_sig[i] - 0.5f * beta_mu[i] * beta_mu[i];
        red[tid] = acc;
        __syncthreads();
        for (int s2 = 128; s2 > 0; s2 >>= 1) {
            if (tid < s2) red[tid] += red[tid + s2];
            __syncthreads();
        }
        if (tid == 0) g_prior = red[0];
        return;
    }

    int warp = (blockIdx.x * blockDim.x + threadIdx.x) >> 5;
    int lane = threadIdx.x & 31;
    if (warp >= N_K * N_T) return;
    int k = warp >> 7;
    int t = warp & (N_T - 1);

    float yv  = __ldg(&y[k * N_T + t]);
    float lam = __ldg(&b_mu[lane]) + __ldg(&beta_mu[lane * N_T + t]) * yv;

    float m = lam;
    #pragma unroll
    for (int o = 16; o > 0; o >>= 1)
        m = fmaxf(m, __shfl_xor_sync(0xffffffffu, m, o));
    float e = __expf(lam - m);
    float ssum = e;
    #pragma unroll
    for (int o = 16; o > 0; o >>= 1)
        ssum += __shfl_xor_sync(0xffffffffu, ssum, o);

    g_logpi[warp * N_C + lane] = lam - m - __logf(ssum);
}

// ---------------------------------------------------------------------------
// Kernel 2: main — 2 spikes/thread, NESTED quad-form evaluation.
// R15 measured the fma floor at 142k cyc/SM with 35% latency slack at 16
// warps; this round targets a 5th CTA (20 warps): logpi loaded as float2
// per 2-comp group (lA/lB 8->4 regs), s9^2 diagonal as a scalar fmaf
// (kills the packed-with-zero pair), __launch_bounds__(128,5) caps 102 regs.
// ---------------------------------------------------------------------------
__global__ void __launch_bounds__(MAIN_BLOCK, 5)
main_kernel(const float* __restrict__ s,
            const int*   __restrict__ ks,
            const int*   __restrict__ ts,
            float*       __restrict__ out) {
    __shared__ __align__(16) u64 sW[N_C * ROWP];
    __shared__ float sred[MAIN_BLOCK];
    __shared__ unsigned int s_isLast;

    for (int i = threadIdx.x; i < N_C * ROWP; i += MAIN_BLOCK)
        sW[i] = g_W[i];
    __syncthreads();

    int nA = blockIdx.x * MAIN_BLOCK + threadIdx.x;
    float lsum = 0.0f;

    if (nA < N_HALF) {
        int nB = nA + N_HALF;

        // Persistent packed operands per spike:
        // 5 s-pairs, 9 splats, 2 sq-pairs, 1 scalar s9^2  (33 regs/spike)
        u64 spA[5], spB[5], splA[9], splB[9], sqA[2], sqB[2];
        float s9sqA, s9sqB;
        {
            float svA[N_D], svB[N_D];
            const float2* pA = (const float2*)(s + (size_t)nA * N_D);
            const float2* pB = (const float2*)(s + (size_t)nB * N_D);
            #pragma unroll
            for (int p = 0; p < 5; p++) {
                float2 a = __ldg(&pA[p]); svA[2*p] = a.x; svA[2*p+1] = a.y;
                float2 b = __ldg(&pB[p]); svB[2*p] = b.x; svB[2*p+1] = b.y;
            }
            #pragma unroll
            for (int p = 0; p < 5; p++) {
                spA[p] = pk2(svA[2*p], svA[2*p+1]);
                spB[p] = pk2(svB[2*p], svB[2*p+1]);
            }
            #pragma unroll
            for (int i = 0; i < 9; i++) {
                splA[i] = pk2(svA[i], svA[i]);
                splB[i] = pk2(svB[i], svB[i]);
            }
            sqA[0] = pk2(svA[1]*svA[1], svA[3]*svA[3]);
            sqA[1] = pk2(svA[5]*svA[5], svA[7]*svA[7]);
            sqB[0] = pk2(svB[1]*svB[1], svB[3]*svB[3]);
            sqB[1] = pk2(svB[5]*svB[5], svB[7]*svB[7]);
            s9sqA = svA[9] * svA[9];
            s9sqB = svB[9] * svB[9];
        }

        const float2* lp2A = (const float2*)(g_logpi +
            ((size_t)(__ldg(&ks[nA]) * N_T + __ldg(&ts[nA]))) * N_C);
        const float2* lp2B = (const float2*)(g_logpi +
            ((size_t)(__ldg(&ks[nB]) * N_T + __ldg(&ts[nB]))) * N_C);

        const ulonglong2* cw2 = reinterpret_cast<const ulonglong2*>(c_W);

        float ssA = 0.0f, ssB = 0.0f;

        #pragma unroll 1
        for (int g = 0; g < 16; g++) {
            float2 lA = __ldg(&lp2A[g]);
            float2 lB = __ldg(&lp2B[g]);

            #pragma unroll
            for (int cc = 0; cc < 2; cc++) {
                int c = g * 2 + cc;
                float lAv = (cc == 0) ? lA.x : lA.y;
                float lBv = (cc == 0) ? lB.x : lB.y;
                const ulonglong2* w2 =
                    reinterpret_cast<const ulonglong2*>(sW + c * ROWP);
                const ulonglong2* cq = cw2 + c * ROWQ;

                u64 qA0 = 0ull, qA1 = 0ull, qB0 = 0ull, qB1 = 0ull;
                u64 tA, tB;
                ulonglong2 w;

                // row 0: pairs p0..p4 (sp0..sp4) -> q0
                w = cq[0];
                tA = mul2(w.x, spA[0]);  tB = mul2(w.x, spB[0]);
                fma2(tA, w.y, spA[1]);   fma2(tB, w.y, spB[1]);
                w = cq[1];
                fma2(tA, w.x, spA[2]);   fma2(tB, w.x, spB[2]);
                fma2(tA, w.y, spA[3]);   fma2(tB, w.y, spB[3]);
                w = cq[2];
                fma2(tA, w.x, spA[4]);   fma2(tB, w.x, spB[4]);
                fma2(qA0, splA[0], tA);  fma2(qB0, splB[0], tB);

                // row 1: p5..p8 (sp1..sp4) -> q1
                tA = mul2(w.y, spA[1]);  tB = mul2(w.y, spB[1]);
                w = cq[3];
                fma2(tA, w.x, spA[2]);   fma2(tB, w.x, spB[2]);
                fma2(tA, w.y, spA[3]);   fma2(tB, w.y, spB[3]);
                w = cq[4];
                fma2(tA, w.x, spA[4]);   fma2(tB, w.x, spB[4]);
                fma2(qA1, splA[1], tA);  fma2(qB1, splB[1], tB);

                // row 2: p9..p12 (sp1..sp4) -> q0
                tA = mul2(w.y, spA[1]);  tB = mul2(w.y, spB[1]);
                w = cq[5];
                fma2(tA, w.x, spA[2]);   fma2(tB, w.x, spB[2]);
                fma2(tA, w.y, spA[3]);   fma2(tB, w.y, spB[3]);
                w = cq[6];
                fma2(tA, w.x, spA[4]);   fma2(tB, w.x, spB[4]);
                fma2(qA0, splA[2], tA);  fma2(qB0, splB[2], tB);

                // row 3: p13..p15 (sp2..sp4) -> q1
                tA = mul2(w.y, spA[2]);  tB = mul2(w.y, spB[2]);
                w = cq[7];
                fma2(tA, w.x, spA[3]);   fma2(tB, w.x, spB[3]);
                fma2(tA, w.y, spA[4]);   fma2(tB, w.y, spB[4]);
                fma2(qA1, splA[3], tA);  fma2(qB1, splB[3], tB);

                // row 4: p16..p18 (sp2..sp4) -> q0
                w = cq[8];
                tA = mul2(w.x, spA[2]);  tB = mul2(w.x, spB[2]);
                fma2(tA, w.y, spA[3]);   fma2(tB, w.y, spB[3]);
                w = cq[9];
                fma2(tA, w.x, spA[4]);   fma2(tB, w.x, spB[4]);
                fma2(qA0, splA[4], tA);  fma2(qB0, splB[4], tB);

                // row 5: p19..p20 (sp3..sp4) -> q1   [const->SMEM boundary]
                tA = mul2(w.y, spA[3]);  tB = mul2(w.y, spB[3]);
                w = w2[10];
                fma2(tA, w.x, spA[4]);   fma2(tB, w.x, spB[4]);
                fma2(qA1, splA[5], tA);  fma2(qB1, splB[5], tB);

                // row 6: p21..p22 (sp3..sp4) -> q0
                tA = mul2(w.y, spA[3]);  tB = mul2(w.y, spB[3]);
                w = w2[11];
                fma2(tA, w.x, spA[4]);   fma2(tB, w.x, spB[4]);
                fma2(qA0, splA[6], tA);  fma2(qB0, splB[6], tB);

                // row 7: p23 (sp4) -> q1
                tA = mul2(w.y, spA[4]);  tB = mul2(w.y, spB[4]);
                fma2(qA1, splA[7], tA);  fma2(qB1, splB[7], tB);

                // row 8: p24 (sp4) -> q0
                w = w2[12];
                tA = mul2(w.x, spA[4]);  tB = mul2(w.x, spB[4]);
                fma2(qA0, splA[8], tA);  fma2(qB0, splB[8], tB);

                // diagonals: p25 (odd 1,3), p26 (odd 5,7) packed; p27 lo = -P99/2 scalar
                fma2(qA1, w.y, sqA[0]);  fma2(qB1, w.y, sqB[0]);
                w = w2[13];
                fma2(qA0, w.x, sqA[1]);  fma2(qB0, w.x, sqB[1]);
                float w99 = upk(w.y).x;

                // linear: p28..p32 vs s-pairs
                w = w2[14];
                fma2(qA0, w.x, spA[0]);  fma2(qB0, w.x, spB[0]);
                fma2(qA1, w.y, spA[1]);  fma2(qB1, w.y, spB[1]);
                w = w2[15];
                fma2(qA0, w.x, spA[2]);  fma2(qB0, w.x, spB[2]);
                fma2(qA1, w.y, spA[3]);  fma2(qB1, w.y, spB[3]);
                w = w2[16];
                fma2(qA0, w.x, spA[4]);  fma2(qB0, w.x, spB[4]);
                float kc = upk(w.y).x;                 // K_c - M

                float2 qA = upk(add2(qA0, qA1));
                float2 qB = upk(add2(qB0, qB1));
                float logitA = fmaf(w99, s9sqA, (qA.x + qA.y) + kc + lAv); // <= ~0
                float logitB = fmaf(w99, s9sqB, (qB.x + qB.y) + kc + lBv);
                ssA += __expf(logitA);
                ssB += __expf(logitB);
            }
        }
        lsum = __logf(fmaxf(ssA, 1e-30f)) + __logf(fmaxf(ssB, 1e-30f));
    }

    sred[threadIdx.x] = lsum;
    __syncthreads();
    #pragma unroll
    for (int s2 = MAIN_BLOCK / 2; s2 > 0; s2 >>= 1) {
        if (threadIdx.x < s2) sred[threadIdx.x] += sred[threadIdx.x + s2];
        __syncthreads();
    }
    if (threadIdx.x == 0) {
        g_partial[blockIdx.x] = sred[0];
        __threadfence();
        unsigned int prev = atomicAdd(&g_count, 1u);
        s_isLast = (prev == (unsigned int)(NBLOCKS - 1)) ? 1u : 0u;
    }
    __syncthreads();

    if (s_isLast) {
        __shared__ double dred[MAIN_BLOCK];
        const volatile float* vp = g_partial;
        double acc = 0.0;
        for (int i = threadIdx.x; i < NBLOCKS; i += MAIN_BLOCK)
            acc += (double)vp[i];
        dred[threadIdx.x] = acc;
        __syncthreads();
        for (int s2 = MAIN_BLOCK / 2; s2 > 0; s2 >>= 1) {
            if (threadIdx.x < s2) dred[threadIdx.x] += dred[threadIdx.x + s2];
            __syncthreads();
        }
        if (threadIdx.x == 0)
            out[0] = (float)(dred[0] + (double)g_prior
                             + (double)N_SPK * (double)g_M);
    }
}

// ---------------------------------------------------------------------------
extern "C" void kernel_launch(void* const* d_in, const int* in_sizes, int n_in,
                              void* d_out, int out_size) {
    const float* s            = (const float*)d_in[0];
    const float* y            = (const float*)d_in[1];
    const int*   ks           = (const int*)  d_in[2];
    const int*   ts           = (const int*)  d_in[3];
    const float* means        = (const float*)d_in[4];
    const float* covs         = (const float*)d_in[5];
    const float* b_mu         = (const float*)d_in[6];
    const float* b_log_sig    = (const float*)d_in[7];
    const float* beta_mu      = (const float*)d_in[8];
    const float* beta_log_sig = (const float*)d_in[9];

    logpi_setup_kernel<<<(N_K * N_T * 32) / 256 + 1, 256>>>(
        y, b_mu, beta_mu, means, covs, b_log_sig, beta_log_sig);

    // Mirror device-computed W into the constant bank (D2D node, capturable).
    void* g_W_addr = nullptr;
    cudaGetSymbolAddress(&g_W_addr, g_W);
    cudaMemcpyToSymbolAsync(c_W, g_W_addr, sizeof(u64) * N_C * ROWP, 0,
                            cudaMemcpyDeviceToDevice);

    main_kernel<<<NBLOCKS, MAIN_BLOCK>>>(s, ks, ts, (float*)d_out);
}